// round 3
// baseline (speedup 1.0000x reference)
#include <cuda_runtime.h>
#include <math.h>

#define N_POINTS 16384
#define MAXNB 64
#define FULL 0xffffffffu

// ---- scratch (device globals; no allocation allowed) ----
__device__ int   d_cloud_start[9];
__device__ int   d_nbr_idx[N_POINTS * MAXNB];
__device__ int   d_nbr_cnt[N_POINTS];
__device__ float d_feat_a[N_POINTS * 8];
__device__ float d_feat_b[N_POINTS * 16];

// ---- kernel 1: per-cloud ranges via binary search (batch is sorted) ----
__global__ void ranges_kernel(const int* __restrict__ batch, int n) {
    int c = threadIdx.x;
    if (c > 8) return;
    int lo = 0, hi = n;
    while (lo < hi) {
        int mid = (lo + hi) >> 1;
        if (batch[mid] < c) lo = mid + 1; else hi = mid;
    }
    d_cloud_start[c] = lo;
}

// ---- kernel 2: warp-per-point brute-force radius search within own cloud ----
__global__ void build_nbrs(const float* __restrict__ pos, const int* __restrict__ batch) {
    int warp = (blockIdx.x * blockDim.x + threadIdx.x) >> 5;
    int lane = threadIdx.x & 31;
    if (warp >= N_POINTS) return;
    const int i = warp;
    const float px = pos[3*i+0], py = pos[3*i+1], pz = pos[3*i+2];
    const float sqi = (px*px + py*py) + pz*pz;     // match jnp.sum(pos*pos) ordering
    const int c  = batch[i];
    const int lo = d_cloud_start[c];
    const int hi = d_cloud_start[c+1];
    const float r2 = (1.0f/16.0f) * (1.0f/16.0f);
    int cnt = 0;  // replicated across lanes
    for (int jb = lo; jb < hi; jb += 32) {
        int j = jb + lane;
        bool ok = false;
        if (j < hi) {
            float qx = pos[3*j+0], qy = pos[3*j+1], qz = pos[3*j+2];
            float sqj = (qx*qx + qy*qy) + qz*qz;
            float dot = px*qx + py*qy + pz*qz;
            float d2  = fmaxf(sqi + sqj - 2.0f*dot, 0.0f);   // exact reference formula
            ok = (d2 <= r2);
        }
        unsigned m = __ballot_sync(FULL, ok);
        if (ok) {
            int off = cnt + __popc(m & ((1u << lane) - 1u));
            if (off < MAXNB) d_nbr_idx[i*MAXNB + off] = j;
        }
        cnt += __popc(m);
    }
    if (lane == 0) d_nbr_cnt[i] = cnt < MAXNB ? cnt : MAXNB;
}

// ---- kernel 3: PointNetConv + celu, warp-per-point, lane=channel (with replicas) ----
// SRC: 0 = pos param (layer a), 1 = d_feat_a, 2 = d_feat_b
// DST: 1 = d_feat_a, 2 = d_feat_b, 3 = out param
template<int CIN, int CMID, int SRC, int DST>
__global__ void conv_kernel(const float* __restrict__ pos,
                            const float* __restrict__ W1, const float* __restrict__ b1,
                            const float* __restrict__ W2, const float* __restrict__ b2,
                            float* __restrict__ outp) {
    constexpr int FIN = CIN + 3;
    __shared__ float sW1[FIN * CMID];
    __shared__ float sW2[CMID * CMID];
    __shared__ float sb1[CMID];
    __shared__ float sb2[CMID];
    for (int t = threadIdx.x; t < FIN * CMID;  t += blockDim.x) sW1[t] = W1[t];
    for (int t = threadIdx.x; t < CMID * CMID; t += blockDim.x) sW2[t] = W2[t];
    for (int t = threadIdx.x; t < CMID;        t += blockDim.x) { sb1[t] = b1[t]; sb2[t] = b2[t]; }
    __syncthreads();

    int warp = (blockIdx.x * blockDim.x + threadIdx.x) >> 5;
    int lane = threadIdx.x & 31;
    if (warp >= N_POINTS) return;
    const int i = warp;
    const int m   = lane % CMID;         // channel
    const int rep = lane / CMID;         // neighbor-group replica
    constexpr int R = 32 / CMID;

    const float* xin = (SRC == 0) ? pos : (SRC == 1) ? d_feat_a : d_feat_b;

    const float px = pos[3*i+0], py = pos[3*i+1], pz = pos[3*i+2];
    const int cnt = d_nbr_cnt[i];

    float best = -INFINITY;
    for (int k = rep; k < cnt; k += R) {
        int j = d_nbr_idx[i*MAXNB + k];
        float s = sb1[m];
        #pragma unroll
        for (int f = 0; f < CIN; f++)
            s += xin[j*CIN + f] * sW1[f*CMID + m];
        float qx = pos[3*j+0], qy = pos[3*j+1], qz = pos[3*j+2];
        s += (qx - px) * sW1[(CIN+0)*CMID + m]
           + (qy - py) * sW1[(CIN+1)*CMID + m]
           + (qz - pz) * sW1[(CIN+2)*CMID + m];
        s = fmaxf(s, 0.0f);              // relu
        best = fmaxf(best, s);           // max aggregation
    }
    // reduce max across replicas (lanes m, m+CMID, ...)
    #pragma unroll
    for (int d = CMID; d < 32; d <<= 1)
        best = fmaxf(best, __shfl_xor_sync(FULL, best, d));
    if (!isfinite(best)) best = 0.0f;    // cnt==0 safety (loop=True makes this moot)

    // second linear: out[o] = celu(sum_m agg[m]*W2[m][o] + b2[o]); lane m holds agg[m]
    float acc = sb2[m];
    #pragma unroll
    for (int mm = 0; mm < CMID; mm++)
        acc += __shfl_sync(FULL, best, mm) * sW2[mm*CMID + m];
    acc = (acc > 0.0f) ? acc : expm1f(acc);   // celu, alpha=1

    if (rep == 0) {
        float* o = (DST == 1) ? d_feat_a : (DST == 2) ? d_feat_b : outp;
        o[i*CMID + m] = acc;
    }
}

// ---- kernel 4: copy pos and batch (as float) into output head/tail ----
__global__ void copy_aux(const float* __restrict__ pos, const int* __restrict__ batch,
                         float* __restrict__ out) {
    int t = blockIdx.x * blockDim.x + threadIdx.x;
    if (t < N_POINTS * 3) out[t] = pos[t];
    if (t < N_POINTS)     out[N_POINTS*3 + N_POINTS*32 + t] = (float)batch[t];
}

extern "C" void kernel_launch(void* const* d_in, const int* in_sizes, int n_in,
                              void* d_out, int out_size) {
    const float* pos   = (const float*)d_in[0];
    // d_in[1] = rgb (unused by the reference)
    const int*   batch = (const int*)d_in[2];
    const float* W1a = (const float*)d_in[3];
    const float* b1a = (const float*)d_in[4];
    const float* W2a = (const float*)d_in[5];
    const float* b2a = (const float*)d_in[6];
    const float* W1b = (const float*)d_in[7];
    const float* b1b = (const float*)d_in[8];
    const float* W2b = (const float*)d_in[9];
    const float* b2b = (const float*)d_in[10];
    const float* W1c = (const float*)d_in[11];
    const float* b1c = (const float*)d_in[12];
    const float* W2c = (const float*)d_in[13];
    const float* b2c = (const float*)d_in[14];

    float* out = (float*)d_out;
    const int full_size = N_POINTS*3 + N_POINTS*32 + N_POINTS;  // pos + feat + batch
    const bool aux = (out_size >= full_size);
    float* feat_out = out + (aux ? N_POINTS*3 : 0);

    ranges_kernel<<<1, 16>>>(batch, N_POINTS);
    build_nbrs<<<(N_POINTS*32 + 255)/256, 256>>>(pos, batch);

    conv_kernel<3,  8,  0, 1><<<(N_POINTS*32 + 255)/256, 256>>>(pos, W1a, b1a, W2a, b2a, nullptr);
    conv_kernel<8,  16, 1, 2><<<(N_POINTS*32 + 255)/256, 256>>>(pos, W1b, b1b, W2b, b2b, nullptr);
    conv_kernel<16, 32, 2, 3><<<(N_POINTS*32 + 255)/256, 256>>>(pos, W1c, b1c, W2c, b2c, feat_out);

    if (aux)
        copy_aux<<<(N_POINTS*3 + 255)/256, 256>>>(pos, batch, out);
}

// round 4
// speedup vs baseline: 2.2900x; 2.2900x over previous
#include <cuda_runtime.h>
#include <math.h>

#define N_PTS 16384
#define MAXNB 64
#define NCLOUD 8
#define GDIM 16
#define NCELLS (NCLOUD*GDIM*GDIM*GDIM)   // 32768
#define CAP 32
#define FULL 0xffffffffu

// ---- scratch (device globals; no allocation allowed) ----
__device__ int    d_count[NCELLS];
__device__ int    d_cell[NCELLS*CAP];
__device__ float4 d_pos4[N_PTS];                 // x,y,z,sq
__device__ int    d_nbr[N_PTS*MAXNB];
__device__ int    d_cnt[N_PTS];
__device__ float  d_ua[N_PTS*8],  d_va[N_PTS*8];
__device__ float  d_ub[N_PTS*16], d_vb[N_PTS*16];
__device__ float  d_uc[N_PTS*32], d_vc[N_PTS*32];

__global__ void zero_counts() {
    int t = blockIdx.x * blockDim.x + threadIdx.x;
    if (t < NCELLS) d_count[t] = 0;
}

// thread-per-point: pack pos4, insert into grid, copy aux outputs
__global__ void fill_grid(const float* __restrict__ pos, const int* __restrict__ batch,
                          float* __restrict__ out, int aux) {
    int i = blockIdx.x * blockDim.x + threadIdx.x;
    if (i >= N_PTS) return;
    float px = pos[3*i+0], py = pos[3*i+1], pz = pos[3*i+2];
    float sq = (px*px + py*py) + pz*pz;          // match jnp.sum(pos*pos) order
    d_pos4[i] = make_float4(px, py, pz, sq);
    int c  = batch[i];
    int cx = min(GDIM-1, (int)(px * GDIM));
    int cy = min(GDIM-1, (int)(py * GDIM));
    int cz = min(GDIM-1, (int)(pz * GDIM));
    int cell = ((c * GDIM + cz) * GDIM + cy) * GDIM + cx;
    int slot = atomicAdd(&d_count[cell], 1);
    if (slot < CAP) d_cell[cell*CAP + slot] = i;
    if (aux) {
        out[3*i+0] = px; out[3*i+1] = py; out[3*i+2] = pz;
        out[N_PTS*3 + N_PTS*32 + i] = (float)c;
    }
}

// thread-per-point: 27-cell stencil radius scan + layer-a u/v prep
__global__ void build_nbrs(const int* __restrict__ batch,
                           const float* __restrict__ W1a, const float* __restrict__ b1a) {
    int i = blockIdx.x * blockDim.x + threadIdx.x;
    if (i >= N_PTS) return;
    float4 p = d_pos4[i];
    const float r2 = (1.0f/16.0f) * (1.0f/16.0f);
    int c  = batch[i];
    int cx = min(GDIM-1, (int)(p.x * GDIM));
    int cy = min(GDIM-1, (int)(p.y * GDIM));
    int cz = min(GDIM-1, (int)(p.z * GDIM));
    int cnt = 0;
    for (int dz = max(cz-1,0); dz <= min(cz+1,GDIM-1); dz++)
    for (int dy = max(cy-1,0); dy <= min(cy+1,GDIM-1); dy++)
    for (int dx = max(cx-1,0); dx <= min(cx+1,GDIM-1); dx++) {
        int cell = ((c * GDIM + dz) * GDIM + dy) * GDIM + dx;
        int m = min(d_count[cell], CAP);
        for (int t = 0; t < m; t++) {
            int j = d_cell[cell*CAP + t];
            float4 q = d_pos4[j];
            float dot = (p.x*q.x + p.y*q.y) + p.z*q.z;
            float d2  = fmaxf(p.w + q.w - 2.0f*dot, 0.0f);   // exact reference formula
            if (d2 <= r2 && cnt < MAXNB) d_nbr[i*MAXNB + cnt++] = j;
        }
    }
    d_cnt[i] = cnt;
    // prep layer a: u_a = b1 + pos@W1x + pos@W1p ; v_a = pos@W1p  (input x == pos)
    #pragma unroll
    for (int m = 0; m < 8; m++) {
        float tf = p.x*W1a[0*8+m] + p.y*W1a[1*8+m] + p.z*W1a[2*8+m];
        float tp = p.x*W1a[3*8+m] + p.y*W1a[4*8+m] + p.z*W1a[5*8+m];
        d_ua[i*8+m] = b1a[m] + tf + tp;
        d_va[i*8+m] = tp;
    }
}

// layer a conv (CMID=8, 4 replicas) + layer b u/v prep (16 ch)
__global__ void conv_ab(const float* __restrict__ W2, const float* __restrict__ b2,
                        const float* __restrict__ W1n, const float* __restrict__ b1n) {
    int warp = (blockIdx.x * blockDim.x + threadIdx.x) >> 5;
    int lane = threadIdx.x & 31;
    if (warp >= N_PTS) return;
    const int i = warp, m = lane & 7, rep = lane >> 3;
    float v = d_va[i*8+m];
    int cnt = d_cnt[i];
    float best = -INFINITY;
    for (int k = rep; k < cnt; k += 4) {
        int j = d_nbr[i*MAXNB + k];
        float s = d_ua[j*8+m] - v;
        best = fmaxf(best, fmaxf(s, 0.0f));
    }
    best = fmaxf(best, __shfl_xor_sync(FULL, best, 8));
    best = fmaxf(best, __shfl_xor_sync(FULL, best, 16));
    if (!isfinite(best)) best = 0.0f;
    float acc = b2[m];
    #pragma unroll
    for (int mm = 0; mm < 8; mm++)
        acc += __shfl_sync(FULL, best, mm) * W2[mm*8+m];
    acc = (acc > 0.0f) ? acc : expm1f(acc);      // celu; lanes 0..7 hold out[0..7]
    // prep layer b on all lanes (mb = lane&15), store from lanes 0..15
    float4 p = d_pos4[i];
    int mb = lane & 15;
    float tp = p.x*W1n[8*16+mb] + p.y*W1n[9*16+mb] + p.z*W1n[10*16+mb];
    float u = b1n[mb] + tp;
    #pragma unroll
    for (int f = 0; f < 8; f++)
        u += __shfl_sync(FULL, acc, f) * W1n[f*16+mb];
    if (lane < 16) { d_ub[i*16+mb] = u; d_vb[i*16+mb] = tp; }
}

// layer b conv (CMID=16, 2 replicas) + layer c u/v prep (32 ch)
__global__ void conv_bc(const float* __restrict__ W2, const float* __restrict__ b2,
                        const float* __restrict__ W1n, const float* __restrict__ b1n) {
    int warp = (blockIdx.x * blockDim.x + threadIdx.x) >> 5;
    int lane = threadIdx.x & 31;
    if (warp >= N_PTS) return;
    const int i = warp, m = lane & 15, rep = lane >> 4;
    float v = d_vb[i*16+m];
    int cnt = d_cnt[i];
    float best = -INFINITY;
    for (int k = rep; k < cnt; k += 2) {
        int j = d_nbr[i*MAXNB + k];
        float s = d_ub[j*16+m] - v;
        best = fmaxf(best, fmaxf(s, 0.0f));
    }
    best = fmaxf(best, __shfl_xor_sync(FULL, best, 16));
    if (!isfinite(best)) best = 0.0f;
    float acc = b2[m];
    #pragma unroll
    for (int mm = 0; mm < 16; mm++)
        acc += __shfl_sync(FULL, best, mm) * W2[mm*16+m];
    acc = (acc > 0.0f) ? acc : expm1f(acc);      // lanes 0..15 hold out[0..15]
    // prep layer c: all 32 lanes, mc = lane
    float4 p = d_pos4[i];
    float tp = p.x*W1n[16*32+lane] + p.y*W1n[17*32+lane] + p.z*W1n[18*32+lane];
    float u = b1n[lane] + tp;
    #pragma unroll
    for (int f = 0; f < 16; f++)
        u += __shfl_sync(FULL, acc, f) * W1n[f*32+lane];
    d_uc[i*32+lane] = u;
    d_vc[i*32+lane] = tp;
}

// layer c conv (CMID=32, 1 replica) -> final output
__global__ void conv_c(const float* __restrict__ W2, const float* __restrict__ b2,
                       float* __restrict__ outp) {
    int warp = (blockIdx.x * blockDim.x + threadIdx.x) >> 5;
    int lane = threadIdx.x & 31;
    if (warp >= N_PTS) return;
    const int i = warp;
    float v = d_vc[i*32+lane];
    int cnt = d_cnt[i];
    float best = -INFINITY;
    for (int k = 0; k < cnt; k++) {
        int j = d_nbr[i*MAXNB + k];
        float s = d_uc[j*32+lane] - v;
        best = fmaxf(best, fmaxf(s, 0.0f));
    }
    if (!isfinite(best)) best = 0.0f;
    float acc = b2[lane];
    #pragma unroll
    for (int mm = 0; mm < 32; mm++)
        acc += __shfl_sync(FULL, best, mm) * W2[mm*32+lane];
    acc = (acc > 0.0f) ? acc : expm1f(acc);
    outp[i*32+lane] = acc;
}

extern "C" void kernel_launch(void* const* d_in, const int* in_sizes, int n_in,
                              void* d_out, int out_size) {
    const float* pos   = (const float*)d_in[0];
    const int*   batch = (const int*)d_in[2];
    const float* W1a = (const float*)d_in[3];
    const float* b1a = (const float*)d_in[4];
    const float* W2a = (const float*)d_in[5];
    const float* b2a = (const float*)d_in[6];
    const float* W1b = (const float*)d_in[7];
    const float* b1b = (const float*)d_in[8];
    const float* W2b = (const float*)d_in[9];
    const float* b2b = (const float*)d_in[10];
    const float* W1c = (const float*)d_in[11];
    const float* b1c = (const float*)d_in[12];
    const float* W2c = (const float*)d_in[13];
    const float* b2c = (const float*)d_in[14];

    float* out = (float*)d_out;
    const int full_size = N_PTS*3 + N_PTS*32 + N_PTS;   // pos + feat + batch
    const int aux = (out_size >= full_size) ? 1 : 0;
    float* feat_out = out + (aux ? N_PTS*3 : 0);

    zero_counts<<<(NCELLS + 255)/256, 256>>>();
    fill_grid<<<(N_PTS + 255)/256, 256>>>(pos, batch, out, aux);
    build_nbrs<<<(N_PTS + 255)/256, 256>>>(batch, W1a, b1a);

    conv_ab<<<(N_PTS*32 + 255)/256, 256>>>(W2a, b2a, W1b, b1b);
    conv_bc<<<(N_PTS*32 + 255)/256, 256>>>(W2b, b2b, W1c, b1c);
    conv_c <<<(N_PTS*32 + 255)/256, 256>>>(W2c, b2c, feat_out);
}